// round 3
// baseline (speedup 1.0000x reference)
#include <cuda_runtime.h>
#include <stdint.h>

#define VOCAB 50257
#define SEQ   512
#define BATCH 8
#define KD    4      // NUM_DRAFTS
#define LD    8      // DRAFT_LEN
#define NROWS 256    // KD*LD*BATCH
#define LOGITS_ELEMS (BATCH * SEQ * VOCAB)
#define GX    4      // v-dimension blocks per row in sampler

// Packed per-row argmax state: (order-mapped float)<<32 | (0xFFFFFFFF - v)
// u64 max => argmax val, first-index tie-break (lowest v wins among equals).
__device__ unsigned long long g_rowpack[NROWS];
__device__ float g_smax[BATCH];
__device__ float g_ssum[BATCH];

// ---- JAX partitionable threefry bits for flat index i (< 2^32):
//      (o0, o1) = threefry2x32(key=(0,42), x0=0, x1=i);  bits = o0 ^ o1
__device__ __forceinline__ uint32_t tf_bits(uint32_t i) {
    const uint32_t ks1 = 42u;
    const uint32_t ks2 = 42u ^ 0x1BD11BDAu;
    uint32_t x0 = 0u;            // 0 + ks0(=0)
    uint32_t x1 = i + ks1;
#define TF_R(r) { x0 += x1; x1 = __funnelshift_l(x1, x1, (r)); x1 ^= x0; }
    TF_R(13) TF_R(15) TF_R(26) TF_R(6)
    x0 += ks1; x1 += ks2 + 1u;
    TF_R(17) TF_R(29) TF_R(16) TF_R(24)
    x0 += ks2; x1 += 2u;                 // + ks0(=0) + 2
    TF_R(13) TF_R(15) TF_R(26) TF_R(6)
    /* x0 += ks0(=0) */ x1 += ks1 + 3u;
    TF_R(17) TF_R(29) TF_R(16) TF_R(24)
    x0 += ks1; x1 += ks2 + 4u;
    TF_R(13) TF_R(15) TF_R(26) TF_R(6)
    x0 += ks2; x1 += 5u;                 // + ks0(=0) + 5
#undef TF_R
    return x0 ^ x1;
}

// Order-preserving float -> uint32 map (total order matching IEEE < on reals)
__device__ __forceinline__ uint32_t fmap(float v) {
    uint32_t u = __float_as_uint(v);
    return (u & 0x80000000u) ? ~u : (u | 0x80000000u);
}

// ---------------- Kernel A: softmax stats for the 8 last-position rows ----------
__global__ void __launch_bounds__(1024)
prep_kernel(const float* __restrict__ logits) {
    int b = blockIdx.x;
    const float* row = logits + ((size_t)b * SEQ + (SEQ - 1)) * VOCAB;
    __shared__ float red[1024];
    int t = threadIdx.x;
    if (b == 0 && t < NROWS) g_rowpack[t] = 0ull;   // reset (graph replay safe)

    float m = -INFINITY;
    for (int v = t; v < VOCAB; v += 1024) m = fmaxf(m, row[v]);
    red[t] = m; __syncthreads();
    for (int s = 512; s > 0; s >>= 1) {
        if (t < s) red[t] = fmaxf(red[t], red[t + s]);
        __syncthreads();
    }
    float mx = red[0];
    __syncthreads();

    float acc = 0.0f;
    for (int v = t; v < VOCAB; v += 1024) acc += expf(row[v] - mx);
    red[t] = acc; __syncthreads();
    for (int s = 512; s > 0; s >>= 1) {
        if (t < s) red[t] += red[t + s];
        __syncthreads();
    }
    if (t == 0) { g_smax[b] = mx; g_ssum[b] = red[0]; }
}

// ---------------- Kernel B: exact gumbel-argmax (libdevice logf path) -----------
__global__ void __launch_bounds__(256)
sample_kernel(const float* __restrict__ logits) {
    int r = blockIdx.y;          // sampling row (k,l,b) flat; b = r & 7
    int b = r & 7;
    const float* __restrict__ row = logits + ((size_t)b * SEQ + (SEQ - 1)) * VOCAB;

    __shared__ unsigned long long sbest;
    if (threadIdx.x == 0) sbest = 0ull;
    __syncthreads();

    const float tiny = 1.17549435e-38f;
    unsigned long long best = 0ull;
    uint32_t base = (uint32_t)r * (uint32_t)VOCAB;
    for (int v = blockIdx.x * 256 + threadIdx.x; v < VOCAB; v += GX * 256) {
        uint32_t bits = tf_bits(base + (uint32_t)v);
        float f = __uint_as_float((bits >> 9) | 0x3f800000u) - 1.0f;  // [0,1)
        float u = fmaxf(tiny, f + tiny);          // JAX uniform(tiny, 1)
        // Exact reference formula via libdevice logf (bit-matches XLA's __nv_logf):
        float val = __ldg(row + v) - logf(-logf(u));   // logit + gumbel
        unsigned long long pk =
            ((unsigned long long)fmap(val) << 32) |
            (unsigned long long)(0xFFFFFFFFu - (uint32_t)v);
        if (pk > best) best = pk;
    }
    atomicMax(&sbest, best);
    __syncthreads();
    if (threadIdx.x == 0) atomicMax(&g_rowpack[r], sbest);
}

// ---------------- Kernel C: epilogue, writes the whole 808-float output ---------
__global__ void __launch_bounds__(NROWS)
finalize_kernel(const float* __restrict__ logits, float* __restrict__ out) {
    __shared__ float probs_s[NROWS];
    __shared__ float meanp_s[BATCH * KD];
    int o = threadIdx.x;                 // output layout (b, k, l)
    int b = o >> 5, k = (o >> 3) & 3, l = o & 7;
    int rowidx = k * 64 + l * 8 + b;     // gumbel-field row (k, l, b)

    unsigned long long pk = g_rowpack[rowidx];
    uint32_t tok = 0xFFFFFFFFu - (uint32_t)(pk & 0xFFFFFFFFull);
    float lg = logits[((size_t)b * SEQ + (SEQ - 1)) * VOCAB + tok];
    float prob = expf(lg - g_smax[b]) / g_ssum[b];

    out[o] = (float)tok;                               // draft_tokens
    out[NROWS + o] = prob;                             // draft_probs
    out[2 * NROWS + o] = (prob >= 0.8f) ? 1.0f : 0.0f; // accepted_mask
    probs_s[o] = prob;
    __syncthreads();

    if (o < BATCH * KD) {                              // (b, k)
        int bb = o >> 2, kk = o & 3;
        float sp = 0.0f, sm = 0.0f;
        #pragma unroll
        for (int ll = 0; ll < LD; ll++) {
            float p = probs_s[bb * 32 + kk * 8 + ll];
            sp += p;
            sm += (p >= 0.8f) ? 1.0f : 0.0f;
        }
        out[3 * NROWS + o] = sm / 8.0f;                // acceptance_ratio
        meanp_s[o] = sp / 8.0f;
    }
    __syncthreads();

    if (o < BATCH) {                                   // best_draft_idx (first max)
        int best = 0;
        float bv = meanp_s[o * 4];
        #pragma unroll
        for (int kk = 1; kk < KD; kk++) {
            float v2 = meanp_s[o * 4 + kk];
            if (v2 > bv) { bv = v2; best = kk; }
        }
        out[3 * NROWS + 32 + o] = (float)best;
    }
}

extern "C" void kernel_launch(void* const* d_in, const int* in_sizes, int n_in,
                              void* d_out, int out_size) {
    int li = 1;
    for (int i = 0; i < n_in; i++) {
        if (in_sizes[i] == LOGITS_ELEMS) { li = i; break; }
    }
    const float* logits = (const float*)d_in[li];
    float* out = (float*)d_out;

    prep_kernel<<<BATCH, 1024>>>(logits);
    dim3 gridB(GX, NROWS);
    sample_kernel<<<gridB, 256>>>(logits);
    finalize_kernel<<<1, NROWS>>>(logits, out);
}